// round 13
// baseline (speedup 1.0000x reference)
#include <cuda_runtime.h>
#include <math.h>

// Problem constants (fixed by the reference)
#define MAXN 50000
#define MAXE 1600000
#define NG   64
#define NBMAX 64   // ceil(MAXN/1024) = 49 <= 64

// ---------------- scratch (static device globals; no allocation) ----------------
__device__ int   g_deg[MAXN];
__device__ int   g_fill[MAXN];       // block-LOCAL fill counters
__device__ int   g_rowptr[MAXN + 1]; // block-LOCAL exclusive scan
__device__ float g_loopsum[MAXN];
__device__ float g_loopattr[MAXN];
__device__ int2  g_csr[MAXE];        // {src, __float_as_int(edge_attr)}
__device__ float g_xlr[MAXN * 128];  // per-node [xl(64) | xr(64)]
__device__ float g_h[MAXN * 64];     // layer-1 output (elu applied)
__device__ float g_pool[NG * 64];
__device__ float g_cnt[NG];
__device__ int   g_bsum[NBMAX];
__device__ int   g_boff[NBMAX];      // exclusive scan of block sums

// ---------------- warp sum (shfl butterfly; redux.f32 NOT on sm_103) ----------------
__device__ __forceinline__ float warp_sum32(float v) {
    v += __shfl_xor_sync(0xffffffffu, v, 16);
    v += __shfl_xor_sync(0xffffffffu, v, 8);
    v += __shfl_xor_sync(0xffffffffu, v, 4);
    v += __shfl_xor_sync(0xffffffffu, v, 2);
    v += __shfl_xor_sync(0xffffffffu, v, 1);
    return v;
}

// ---------------- init: zero degree/loopsum/pool/cnt ----------------
__global__ void init_kernel(int n) {
    int i = blockIdx.x * blockDim.x + threadIdx.x;
    if (i < n) { g_deg[i] = 0; g_loopsum[i] = 0.f; }
    if (i < NG * 64) g_pool[i] = 0.f;
    if (i < NG) g_cnt[i] = 0.f;
}

// ---------------- count in-degree + sum edge_attr by dst ----------------
__global__ void count_kernel(const int* __restrict__ edge_index,
                             const float* __restrict__ ea, int ne) {
    int i = blockIdx.x * blockDim.x + threadIdx.x;
    if (i >= ne) return;
    int dst = __ldg(edge_index + ne + i);
    atomicAdd(&g_deg[dst], 1);
    atomicAdd(&g_loopsum[dst], __ldg(ea + i));
}

// ---------------- scan A: block-local exclusive scan + block sums + loopattr + cnt --
__global__ __launch_bounds__(1024) void scanA_kernel(const int* __restrict__ batch, int n) {
    __shared__ int sh[1024];
    int t = threadIdx.x;
    int i = blockIdx.x * 1024 + t;
    int v = (i < n) ? g_deg[i] : 0;
    sh[t] = v;
    __syncthreads();
    #pragma unroll
    for (int off = 1; off < 1024; off <<= 1) {
        int add = (t >= off) ? sh[t - off] : 0;
        __syncthreads();
        sh[t] += add;
        __syncthreads();
    }
    if (i < n) {
        int excl = sh[t] - v;            // block-local exclusive
        g_rowptr[i] = excl;
        g_fill[i]   = excl;
        g_loopattr[i] = g_loopsum[i] / fmaxf((float)v, 1.0f);
        atomicAdd(&g_cnt[batch[i]], 1.0f);
        if (i == n - 1) g_rowptr[n] = sh[t];   // block-local inclusive at tail
    }
    if (t == 1023) g_bsum[blockIdx.x] = sh[1023];
}

// ---------------- scan B: scan the (<=64) block sums -> g_boff ----------------
__global__ void bscan_kernel(int nb) {
    __shared__ int sh[NBMAX];
    int t = threadIdx.x;   // blockDim = 64
    int v = (t < nb) ? g_bsum[t] : 0;
    sh[t] = v;
    __syncthreads();
    #pragma unroll
    for (int off = 1; off < NBMAX; off <<= 1) {
        int add = (t >= off) ? sh[t - off] : 0;
        __syncthreads();
        sh[t] += add;
        __syncthreads();
    }
    g_boff[t] = sh[t] - v;          // exclusive
}

// ---------------- scatter edges into CSR (by dst), packed 8B ----------------
__global__ void scatter_kernel(const int* __restrict__ edge_index,
                               const float* __restrict__ ea, int ne) {
    int i = blockIdx.x * blockDim.x + threadIdx.x;
    if (i >= ne) return;
    int dst = __ldg(edge_index + ne + i);
    int src = __ldg(edge_index + i);
    int pos = atomicAdd(&g_fill[dst], 1) + g_boff[dst >> 10];
    g_csr[pos] = make_int2(src, __float_as_int(__ldg(ea + i)));
}

// ---------------- dual GEMM: out[n,128] = [A@Wl+bl | A@Wr+br] ----------------
template <int K>
__global__ __launch_bounds__(256) void gemm_dual(
    const float* __restrict__ Aext, int useH,
    const float* __restrict__ Wl, const float* __restrict__ bl,
    const float* __restrict__ Wr, const float* __restrict__ br, int n)
{
    __shared__ float Ws[64 * 128];
    __shared__ float bs[128];
    const float* __restrict__ A = useH ? g_h : Aext;
    int tid = threadIdx.x;
    if (tid < 128) bs[tid] = (tid < 64) ? bl[tid] : br[tid - 64];
    int cg = tid & 15;          // col group -> cols cg*8 .. cg*8+7
    int rg = tid >> 4;          // row group -> rows rg*4 ..
    int row0 = blockIdx.x * 64 + rg * 4;
    int rmax = n - 1;

    float acc[4][8];
    #pragma unroll
    for (int r = 0; r < 4; r++)
        #pragma unroll
        for (int j = 0; j < 8; j++) acc[r][j] = 0.f;

    for (int ks = 0; ks < K; ks += 64) {
        __syncthreads();
        #pragma unroll 4
        for (int idx = tid; idx < 64 * 128; idx += 256) {
            int k = idx >> 7, c = idx & 127;
            Ws[idx] = (c < 64) ? Wl[(ks + k) * 64 + c] : Wr[(ks + k) * 64 + (c - 64)];
        }
        __syncthreads();
        #pragma unroll 2
        for (int k = 0; k < 64; k += 4) {
            float a_r[4][4];
            #pragma unroll
            for (int r = 0; r < 4; r++) {
                int row = row0 + r; if (row > rmax) row = rmax;
                float4 v = *reinterpret_cast<const float4*>(A + row * K + ks + k);
                a_r[r][0] = v.x; a_r[r][1] = v.y; a_r[r][2] = v.z; a_r[r][3] = v.w;
            }
            #pragma unroll
            for (int kk = 0; kk < 4; kk++) {
                float4 w0 = *reinterpret_cast<const float4*>(Ws + (k + kk) * 128 + cg * 8);
                float4 w1 = *reinterpret_cast<const float4*>(Ws + (k + kk) * 128 + cg * 8 + 4);
                #pragma unroll
                for (int r = 0; r < 4; r++) {
                    float av = a_r[r][kk];
                    acc[r][0] += av * w0.x; acc[r][1] += av * w0.y;
                    acc[r][2] += av * w0.z; acc[r][3] += av * w0.w;
                    acc[r][4] += av * w1.x; acc[r][5] += av * w1.y;
                    acc[r][6] += av * w1.z; acc[r][7] += av * w1.w;
                }
            }
        }
    }
    #pragma unroll
    for (int r = 0; r < 4; r++) {
        int row = row0 + r;
        if (row < n) {
            float4 o0 = make_float4(acc[r][0] + bs[cg * 8 + 0], acc[r][1] + bs[cg * 8 + 1],
                                    acc[r][2] + bs[cg * 8 + 2], acc[r][3] + bs[cg * 8 + 3]);
            float4 o1 = make_float4(acc[r][4] + bs[cg * 8 + 4], acc[r][5] + bs[cg * 8 + 5],
                                    acc[r][6] + bs[cg * 8 + 6], acc[r][7] + bs[cg * 8 + 7]);
            *reinterpret_cast<float4*>(g_xlr + row * 128 + cg * 8) = o0;
            *reinterpret_cast<float4*>(g_xlr + row * 128 + cg * 8 + 4) = o1;
        }
    }
}

// ---------------- GATv2 aggregation: warp/node, 2 edges per warp step ----------------
// Half-warp per edge (16 lanes x 4 channels). The 4-level shfl reduction, the exp,
// the CSR load, and loop overhead are all shared by 2 edges -> ~30% fewer
// warp-instructions per edge than the 32-lane/edge version. Unshifted softmax is
// exact here (|logit| <~ 20 << 88). leaky_relu(t) == max(t, 0.2*t).
__global__ __launch_bounds__(256) void gatv2_agg(
    const float* __restrict__ We, const float* __restrict__ att,
    const float* __restrict__ bias, const int* __restrict__ batch,
    int pool_mode, int n)
{
    int i = (blockIdx.x * blockDim.x + threadIdx.x) >> 5;
    int lane = threadIdx.x & 31;
    if (i >= n) return;
    int half = lane >> 4;         // 0 -> edge A, 1 -> edge B
    int cl = (lane & 15) << 2;    // channels cl..cl+3

    float4 xr = *reinterpret_cast<const float4*>(g_xlr + i * 128 + 64 + cl);
    float4 we = *reinterpret_cast<const float4*>(We + cl);
    float4 at = *reinterpret_cast<const float4*>(att + cl);
    int beg = g_rowptr[i]     + g_boff[i >> 10];
    int end = g_rowptr[i + 1] + g_boff[(i + 1) >> 10];
    float la = g_loopattr[i];
    int total = end - beg + 1;    // + self loop (virtual edge at index total-1)

    float d = 0.f;
    float4 acc = make_float4(0.f, 0.f, 0.f, 0.f);

    for (int k = 0; k < total; k += 2) {
        int e = beg + k + half;
        int s = i; float ea = la;                      // e >= end -> self loop / dummy
        if (e < end) { int2 t = __ldg(&g_csr[e]); s = t.x; ea = __int_as_float(t.y); }
        float4 xl = *reinterpret_cast<const float4*>(g_xlr + s * 128 + cl);

        float t0 = xl.x + fmaf(ea, we.x, xr.x);
        float t1 = xl.y + fmaf(ea, we.y, xr.y);
        float t2 = xl.z + fmaf(ea, we.z, xr.z);
        float t3 = xl.w + fmaf(ea, we.w, xr.w);
        t0 = fmaxf(t0, 0.2f * t0);
        t1 = fmaxf(t1, 0.2f * t1);
        t2 = fmaxf(t2, 0.2f * t2);
        t3 = fmaxf(t3, 0.2f * t3);
        float q = fmaf(t0, at.x, fmaf(t1, at.y, fmaf(t2, at.z, t3 * at.w)));
        // reduce within each 16-lane half (xor < 16 never crosses the half boundary)
        q += __shfl_xor_sync(0xffffffffu, q, 8);
        q += __shfl_xor_sync(0xffffffffu, q, 4);
        q += __shfl_xor_sync(0xffffffffu, q, 2);
        q += __shfl_xor_sync(0xffffffffu, q, 1);

        float p = (k + half < total) ? __expf(q) : 0.f;
        d += p;
        acc.x = fmaf(p, xl.x, acc.x);
        acc.y = fmaf(p, xl.y, acc.y);
        acc.z = fmaf(p, xl.z, acc.z);
        acc.w = fmaf(p, xl.w, acc.w);
    }

    // combine the two halves (lane l <-> l^16 hold the same channels)
    d     += __shfl_xor_sync(0xffffffffu, d, 16);
    acc.x += __shfl_xor_sync(0xffffffffu, acc.x, 16);
    acc.y += __shfl_xor_sync(0xffffffffu, acc.y, 16);
    acc.z += __shfl_xor_sync(0xffffffffu, acc.z, 16);
    acc.w += __shfl_xor_sync(0xffffffffu, acc.w, 16);

    float inv = 1.f / (d + 1e-16f);
    float4 bi = *reinterpret_cast<const float4*>(bias + cl);
    float o0 = fmaf(acc.x, inv, bi.x);
    float o1 = fmaf(acc.y, inv, bi.y);
    float o2 = fmaf(acc.z, inv, bi.z);
    float o3 = fmaf(acc.w, inv, bi.w);
    o0 = o0 > 0.f ? o0 : expm1f(o0);      // ELU
    o1 = o1 > 0.f ? o1 : expm1f(o1);
    o2 = o2 > 0.f ? o2 : expm1f(o2);
    o3 = o3 > 0.f ? o3 : expm1f(o3);

    if (half == 0) {                       // lanes 0-15 own the write
        if (pool_mode) {
            int g = batch[i];
            atomicAdd(&g_pool[g * 64 + cl],     o0);
            atomicAdd(&g_pool[g * 64 + cl + 1], o1);
            atomicAdd(&g_pool[g * 64 + cl + 2], o2);
            atomicAdd(&g_pool[g * 64 + cl + 3], o3);
        } else {
            *reinterpret_cast<float4*>(g_h + i * 64 + cl) = make_float4(o0, o1, o2, o3);
        }
    }
}

// ---------------- MLP head: one block per graph ----------------
__global__ void head_kernel(const float* __restrict__ Wfc1, const float* __restrict__ bfc1,
                            const float* __restrict__ gamma, const float* __restrict__ beta,
                            const float* __restrict__ mean,  const float* __restrict__ var,
                            const float* __restrict__ Wfc3,  const float* __restrict__ bfc3,
                            float* __restrict__ out)
{
    int g = blockIdx.x;
    int j = threadIdx.x;          // 0..31 hidden unit
    float invc = 1.f / fmaxf(g_cnt[g], 1.f);
    float t = bfc1[j];
    #pragma unroll
    for (int c = 0; c < 64; c++)
        t += g_pool[g * 64 + c] * invc * Wfc1[c * 32 + j];
    t = fmaxf(t, 0.f);
    t = (t - mean[j]) * (1.f / sqrtf(var[j] + 1e-5f)) * gamma[j] + beta[j];
    float contrib = warp_sum32(t * Wfc3[j]);
    if (j == 0) out[g] = contrib + bfc3[0];
}

// ---------------- launch ----------------
extern "C" void kernel_launch(void* const* d_in, const int* in_sizes, int n_in,
                              void* d_out, int out_size) {
    const float* x          = (const float*)d_in[0];
    const int*   edge_index = (const int*)  d_in[1];
    const float* edge_attr  = (const float*)d_in[2];
    const int*   batch      = (const int*)  d_in[3];
    const float* Wl1  = (const float*)d_in[4];
    const float* bl1  = (const float*)d_in[5];
    const float* Wr1  = (const float*)d_in[6];
    const float* br1  = (const float*)d_in[7];
    const float* We1  = (const float*)d_in[8];
    const float* att1 = (const float*)d_in[9];
    const float* bias1= (const float*)d_in[10];
    const float* Wl2  = (const float*)d_in[11];
    const float* bl2  = (const float*)d_in[12];
    const float* Wr2  = (const float*)d_in[13];
    const float* br2  = (const float*)d_in[14];
    const float* We2  = (const float*)d_in[15];
    const float* att2 = (const float*)d_in[16];
    const float* bias2= (const float*)d_in[17];
    const float* Wfc1 = (const float*)d_in[18];
    const float* bfc1 = (const float*)d_in[19];
    const float* gamma= (const float*)d_in[20];
    const float* beta = (const float*)d_in[21];
    const float* mean = (const float*)d_in[22];
    const float* var  = (const float*)d_in[23];
    const float* Wfc3 = (const float*)d_in[24];
    const float* bfc3 = (const float*)d_in[25];

    int n  = in_sizes[0] / 128;
    int ne = in_sizes[1] / 2;
    int nb = (n + 1023) / 1024;

    // CSR build (block-local scan + per-block offsets)
    init_kernel<<<(n + 255) / 256, 256>>>(n);
    count_kernel<<<(ne + 255) / 256, 256>>>(edge_index, edge_attr, ne);
    scanA_kernel<<<nb, 1024>>>(batch, n);
    bscan_kernel<<<1, NBMAX>>>(nb);
    scatter_kernel<<<(ne + 255) / 256, 256>>>(edge_index, edge_attr, ne);

    int gemm_blocks = (n + 63) / 64;
    int warp_blocks = (n + 7) / 8;    // 8 warps per 256-thread block

    // Layer 1
    gemm_dual<128><<<gemm_blocks, 256>>>(x, 0, Wl1, bl1, Wr1, br1, n);
    gatv2_agg<<<warp_blocks, 256>>>(We1, att1, bias1, batch, 0, n);
    // Layer 2 (pool fused into epilogue)
    gemm_dual<64><<<gemm_blocks, 256>>>(x, 1, Wl2, bl2, Wr2, br2, n);
    gatv2_agg<<<warp_blocks, 256>>>(We2, att2, bias2, batch, 1, n);

    // Head
    head_kernel<<<NG, 32>>>(Wfc1, bfc1, gamma, beta, mean, var, Wfc3, bfc3,
                            (float*)d_out);
}

// round 17
// speedup vs baseline: 1.2600x; 1.2600x over previous
#include <cuda_runtime.h>
#include <math.h>

// Problem constants (fixed by the reference)
#define MAXN 50000
#define MAXE 1600000
#define NG   64
#define NBMAX 64   // ceil(MAXN/1024) = 49 <= 64

// ---------------- scratch (static device globals; no allocation) ----------------
__device__ int   g_deg[MAXN];
__device__ int   g_fill[MAXN];       // block-LOCAL fill counters
__device__ int   g_rowptr[MAXN + 1]; // block-LOCAL exclusive scan
__device__ float g_loopsum[MAXN];
__device__ float g_loopattr[MAXN];
__device__ int2  g_csr[MAXE];        // {src, __float_as_int(edge_attr)}
__device__ float g_xlr[MAXN * 128];  // per-node [xl(64) | xr(64)]
__device__ float g_h[MAXN * 64];     // layer-1 output (elu applied)
__device__ float g_pool[NG * 64];
__device__ float g_cnt[NG];
__device__ int   g_bsum[NBMAX];
__device__ int   g_boff[NBMAX];      // exclusive scan of block sums

// ---------------- warp sum (shfl butterfly; redux.f32 NOT on sm_103) ----------------
__device__ __forceinline__ float warp_sum32(float v) {
    v += __shfl_xor_sync(0xffffffffu, v, 16);
    v += __shfl_xor_sync(0xffffffffu, v, 8);
    v += __shfl_xor_sync(0xffffffffu, v, 4);
    v += __shfl_xor_sync(0xffffffffu, v, 2);
    v += __shfl_xor_sync(0xffffffffu, v, 1);
    return v;
}

// ---------------- init: zero degree/loopsum/pool/cnt ----------------
__global__ void init_kernel(int n) {
    int i = blockIdx.x * blockDim.x + threadIdx.x;
    if (i < n) { g_deg[i] = 0; g_loopsum[i] = 0.f; }
    if (i < NG * 64) g_pool[i] = 0.f;
    if (i < NG) g_cnt[i] = 0.f;
}

// ---------------- count in-degree + sum edge_attr by dst ----------------
__global__ void count_kernel(const int* __restrict__ edge_index,
                             const float* __restrict__ ea, int ne) {
    int i = blockIdx.x * blockDim.x + threadIdx.x;
    if (i >= ne) return;
    int dst = __ldg(edge_index + ne + i);
    atomicAdd(&g_deg[dst], 1);
    atomicAdd(&g_loopsum[dst], __ldg(ea + i));
}

// ---------------- scan A: block-local exclusive scan + block sums + loopattr + cnt --
__global__ __launch_bounds__(1024) void scanA_kernel(const int* __restrict__ batch, int n) {
    __shared__ int sh[1024];
    int t = threadIdx.x;
    int i = blockIdx.x * 1024 + t;
    int v = (i < n) ? g_deg[i] : 0;
    sh[t] = v;
    __syncthreads();
    #pragma unroll
    for (int off = 1; off < 1024; off <<= 1) {
        int add = (t >= off) ? sh[t - off] : 0;
        __syncthreads();
        sh[t] += add;
        __syncthreads();
    }
    if (i < n) {
        int excl = sh[t] - v;            // block-local exclusive
        g_rowptr[i] = excl;
        g_fill[i]   = excl;
        g_loopattr[i] = g_loopsum[i] / fmaxf((float)v, 1.0f);
        atomicAdd(&g_cnt[batch[i]], 1.0f);
        if (i == n - 1) g_rowptr[n] = sh[t];   // block-local inclusive at tail
    }
    if (t == 1023) g_bsum[blockIdx.x] = sh[1023];
}

// ---------------- scan B: scan the (<=64) block sums -> g_boff ----------------
__global__ void bscan_kernel(int nb) {
    __shared__ int sh[NBMAX];
    int t = threadIdx.x;   // blockDim = 64
    int v = (t < nb) ? g_bsum[t] : 0;
    sh[t] = v;
    __syncthreads();
    #pragma unroll
    for (int off = 1; off < NBMAX; off <<= 1) {
        int add = (t >= off) ? sh[t - off] : 0;
        __syncthreads();
        sh[t] += add;
        __syncthreads();
    }
    g_boff[t] = sh[t] - v;          // exclusive
}

// ---------------- scatter edges into CSR (by dst), packed 8B ----------------
__global__ void scatter_kernel(const int* __restrict__ edge_index,
                               const float* __restrict__ ea, int ne) {
    int i = blockIdx.x * blockDim.x + threadIdx.x;
    if (i >= ne) return;
    int dst = __ldg(edge_index + ne + i);
    int src = __ldg(edge_index + i);
    int pos = atomicAdd(&g_fill[dst], 1) + g_boff[dst >> 10];
    g_csr[pos] = make_int2(src, __float_as_int(__ldg(ea + i)));
}

// ---------------- dual GEMM: out[n,128] = [A@Wl+bl | A@Wr+br] ----------------
template <int K>
__global__ __launch_bounds__(256) void gemm_dual(
    const float* __restrict__ Aext, int useH,
    const float* __restrict__ Wl, const float* __restrict__ bl,
    const float* __restrict__ Wr, const float* __restrict__ br, int n)
{
    __shared__ float Ws[64 * 128];
    __shared__ float bs[128];
    const float* __restrict__ A = useH ? g_h : Aext;
    int tid = threadIdx.x;
    if (tid < 128) bs[tid] = (tid < 64) ? bl[tid] : br[tid - 64];
    int cg = tid & 15;          // col group -> cols cg*8 .. cg*8+7
    int rg = tid >> 4;          // row group -> rows rg*4 ..
    int row0 = blockIdx.x * 64 + rg * 4;
    int rmax = n - 1;

    float acc[4][8];
    #pragma unroll
    for (int r = 0; r < 4; r++)
        #pragma unroll
        for (int j = 0; j < 8; j++) acc[r][j] = 0.f;

    for (int ks = 0; ks < K; ks += 64) {
        __syncthreads();
        #pragma unroll 4
        for (int idx = tid; idx < 64 * 128; idx += 256) {
            int k = idx >> 7, c = idx & 127;
            Ws[idx] = (c < 64) ? Wl[(ks + k) * 64 + c] : Wr[(ks + k) * 64 + (c - 64)];
        }
        __syncthreads();
        #pragma unroll 2
        for (int k = 0; k < 64; k += 4) {
            float a_r[4][4];
            #pragma unroll
            for (int r = 0; r < 4; r++) {
                int row = row0 + r; if (row > rmax) row = rmax;
                float4 v = *reinterpret_cast<const float4*>(A + row * K + ks + k);
                a_r[r][0] = v.x; a_r[r][1] = v.y; a_r[r][2] = v.z; a_r[r][3] = v.w;
            }
            #pragma unroll
            for (int kk = 0; kk < 4; kk++) {
                float4 w0 = *reinterpret_cast<const float4*>(Ws + (k + kk) * 128 + cg * 8);
                float4 w1 = *reinterpret_cast<const float4*>(Ws + (k + kk) * 128 + cg * 8 + 4);
                #pragma unroll
                for (int r = 0; r < 4; r++) {
                    float av = a_r[r][kk];
                    acc[r][0] += av * w0.x; acc[r][1] += av * w0.y;
                    acc[r][2] += av * w0.z; acc[r][3] += av * w0.w;
                    acc[r][4] += av * w1.x; acc[r][5] += av * w1.y;
                    acc[r][6] += av * w1.z; acc[r][7] += av * w1.w;
                }
            }
        }
    }
    #pragma unroll
    for (int r = 0; r < 4; r++) {
        int row = row0 + r;
        if (row < n) {
            float4 o0 = make_float4(acc[r][0] + bs[cg * 8 + 0], acc[r][1] + bs[cg * 8 + 1],
                                    acc[r][2] + bs[cg * 8 + 2], acc[r][3] + bs[cg * 8 + 3]);
            float4 o1 = make_float4(acc[r][4] + bs[cg * 8 + 4], acc[r][5] + bs[cg * 8 + 5],
                                    acc[r][6] + bs[cg * 8 + 6], acc[r][7] + bs[cg * 8 + 7]);
            *reinterpret_cast<float4*>(g_xlr + row * 128 + cg * 8) = o0;
            *reinterpret_cast<float4*>(g_xlr + row * 128 + cg * 8 + 4) = o1;
        }
    }
}

// ---------------- GATv2 aggregation: warp per dst node, unshifted softmax ----------------
// Structure proven fastest (R7): warp-uniform edge per iteration, 2 ch/lane, no manual
// pipelining (TLP hides the L2 gather latency), separate self-loop epilogue.
// Unshifted softmax is exact here (|logit| <~ 20 << 88). leaky(t) == max(t, 0.2t).
__global__ __launch_bounds__(256) void gatv2_agg(
    const float* __restrict__ We, const float* __restrict__ att,
    const float* __restrict__ bias, const int* __restrict__ batch,
    int pool_mode, int n)
{
    int i = (blockIdx.x * blockDim.x + threadIdx.x) >> 5;
    int lane = threadIdx.x & 31;
    if (i >= n) return;
    int c = 2 * lane;           // cols c, c+1

    float2 xr = *reinterpret_cast<const float2*>(g_xlr + i * 128 + 64 + c);
    float2 we = *reinterpret_cast<const float2*>(We + c);
    float2 at = *reinterpret_cast<const float2*>(att + c);

    float d = 0.f, a0 = 0.f, a1 = 0.f;
    int beg = g_rowptr[i]     + g_boff[i >> 10];
    int end = g_rowptr[i + 1] + g_boff[(i + 1) >> 10];

    for (int e = beg; e < end; ++e) {
        int2 se = __ldg(&g_csr[e]);
        int s = se.x;
        float ea = __int_as_float(se.y);
        float2 xl = *reinterpret_cast<const float2*>(g_xlr + s * 128 + c);
        float t0 = xl.x + fmaf(ea, we.x, xr.x);
        float t1 = xl.y + fmaf(ea, we.y, xr.y);
        t0 = fmaxf(t0, 0.2f * t0);
        t1 = fmaxf(t1, 0.2f * t1);
        float part = fmaf(t0, at.x, t1 * at.y);
        part += __shfl_xor_sync(0xffffffffu, part, 16);
        part += __shfl_xor_sync(0xffffffffu, part, 8);
        part += __shfl_xor_sync(0xffffffffu, part, 4);
        part += __shfl_xor_sync(0xffffffffu, part, 2);
        part += __shfl_xor_sync(0xffffffffu, part, 1);
        float p = __expf(part);
        d += p;
        a0 = fmaf(p, xl.x, a0);
        a1 = fmaf(p, xl.y, a1);
    }
    { // self loop (appended after real edges, matching PyG add_self_loops)
        float ea = g_loopattr[i];
        float2 xl = *reinterpret_cast<const float2*>(g_xlr + i * 128 + c);
        float t0 = xl.x + fmaf(ea, we.x, xr.x);
        float t1 = xl.y + fmaf(ea, we.y, xr.y);
        t0 = fmaxf(t0, 0.2f * t0);
        t1 = fmaxf(t1, 0.2f * t1);
        float part = fmaf(t0, at.x, t1 * at.y);
        part += __shfl_xor_sync(0xffffffffu, part, 16);
        part += __shfl_xor_sync(0xffffffffu, part, 8);
        part += __shfl_xor_sync(0xffffffffu, part, 4);
        part += __shfl_xor_sync(0xffffffffu, part, 2);
        part += __shfl_xor_sync(0xffffffffu, part, 1);
        float p = __expf(part);
        d += p;
        a0 = fmaf(p, xl.x, a0);
        a1 = fmaf(p, xl.y, a1);
    }

    float inv = 1.f / (d + 1e-16f);
    float2 bi = *reinterpret_cast<const float2*>(bias + c);
    float o0 = a0 * inv + bi.x;
    float o1 = a1 * inv + bi.y;
    o0 = o0 > 0.f ? o0 : expm1f(o0);      // ELU
    o1 = o1 > 0.f ? o1 : expm1f(o1);

    if (pool_mode) {
        int g = batch[i];
        atomicAdd(&g_pool[g * 64 + c],     o0);
        atomicAdd(&g_pool[g * 64 + c + 1], o1);
    } else {
        *reinterpret_cast<float2*>(g_h + i * 64 + c) = make_float2(o0, o1);
    }
}

// ---------------- MLP head: one block per graph ----------------
__global__ void head_kernel(const float* __restrict__ Wfc1, const float* __restrict__ bfc1,
                            const float* __restrict__ gamma, const float* __restrict__ beta,
                            const float* __restrict__ mean,  const float* __restrict__ var,
                            const float* __restrict__ Wfc3,  const float* __restrict__ bfc3,
                            float* __restrict__ out)
{
    int g = blockIdx.x;
    int j = threadIdx.x;          // 0..31 hidden unit
    float invc = 1.f / fmaxf(g_cnt[g], 1.f);
    float t = bfc1[j];
    #pragma unroll
    for (int c = 0; c < 64; c++)
        t += g_pool[g * 64 + c] * invc * Wfc1[c * 32 + j];
    t = fmaxf(t, 0.f);
    t = (t - mean[j]) * (1.f / sqrtf(var[j] + 1e-5f)) * gamma[j] + beta[j];
    float contrib = warp_sum32(t * Wfc3[j]);
    if (j == 0) out[g] = contrib + bfc3[0];
}

// ---------------- launch ----------------
extern "C" void kernel_launch(void* const* d_in, const int* in_sizes, int n_in,
                              void* d_out, int out_size) {
    const float* x          = (const float*)d_in[0];
    const int*   edge_index = (const int*)  d_in[1];
    const float* edge_attr  = (const float*)d_in[2];
    const int*   batch      = (const int*)  d_in[3];
    const float* Wl1  = (const float*)d_in[4];
    const float* bl1  = (const float*)d_in[5];
    const float* Wr1  = (const float*)d_in[6];
    const float* br1  = (const float*)d_in[7];
    const float* We1  = (const float*)d_in[8];
    const float* att1 = (const float*)d_in[9];
    const float* bias1= (const float*)d_in[10];
    const float* Wl2  = (const float*)d_in[11];
    const float* bl2  = (const float*)d_in[12];
    const float* Wr2  = (const float*)d_in[13];
    const float* br2  = (const float*)d_in[14];
    const float* We2  = (const float*)d_in[15];
    const float* att2 = (const float*)d_in[16];
    const float* bias2= (const float*)d_in[17];
    const float* Wfc1 = (const float*)d_in[18];
    const float* bfc1 = (const float*)d_in[19];
    const float* gamma= (const float*)d_in[20];
    const float* beta = (const float*)d_in[21];
    const float* mean = (const float*)d_in[22];
    const float* var  = (const float*)d_in[23];
    const float* Wfc3 = (const float*)d_in[24];
    const float* bfc3 = (const float*)d_in[25];

    int n  = in_sizes[0] / 128;
    int ne = in_sizes[1] / 2;
    int nb = (n + 1023) / 1024;

    // CSR build (block-local scan + per-block offsets)
    init_kernel<<<(n + 255) / 256, 256>>>(n);
    count_kernel<<<(ne + 255) / 256, 256>>>(edge_index, edge_attr, ne);
    scanA_kernel<<<nb, 1024>>>(batch, n);
    bscan_kernel<<<1, NBMAX>>>(nb);
    scatter_kernel<<<(ne + 255) / 256, 256>>>(edge_index, edge_attr, ne);

    int gemm_blocks = (n + 63) / 64;
    int warp_blocks = (n + 7) / 8;    // 8 warps per 256-thread block

    // Layer 1
    gemm_dual<128><<<gemm_blocks, 256>>>(x, 0, Wl1, bl1, Wr1, br1, n);
    gatv2_agg<<<warp_blocks, 256>>>(We1, att1, bias1, batch, 0, n);
    // Layer 2 (pool fused into epilogue)
    gemm_dual<64><<<gemm_blocks, 256>>>(x, 1, Wl2, bl2, Wr2, br2, n);
    gatv2_agg<<<warp_blocks, 256>>>(We2, att2, bias2, batch, 1, n);

    // Head
    head_kernel<<<NG, 32>>>(Wfc1, bfc1, gamma, beta, mean, var, Wfc3, bfc3,
                            (float*)d_out);
}